// round 16
// baseline (speedup 1.0000x reference)
#include <cuda_runtime.h>
#include <cuda_bf16.h>
#include <math.h>

#define N_NODES   100000
#define N_EDGES   1600000
#define IN_CH     128
#define HID       64
#define OUT_CH    10
#define NGRAPH    256

// -------- scratch (device globals: no runtime allocation) --------
__device__ __align__(16) float g_h[N_NODES * HID];     // 25.6 MB, holds h*dinv[row]
__device__ __align__(16) float g_agg[N_NODES * HID];   // 25.6 MB
__device__ __align__(16) float g_dinv[N_NODES];
__device__ __align__(16) int   g_deg[N_NODES];
__device__ __align__(16) int   g_rowptr[N_NODES + 1];
__device__ __align__(16) int   g_wpos[N_NODES];
__device__ __align__(16) int   g_esrc[N_EDGES];        // 6.4 MB CSR src bins
__device__ __align__(16) float g_pooled[NGRAPH * HID];
__device__ __align__(16) float g_cnt[NGRAPH];
__device__ int g_is64;

// -------- 1. zero small scratch (deg, pooled, cnt) + detect index width ---
__global__ void zero_kernel(const unsigned int* __restrict__ e) {
    int i = blockIdx.x * blockDim.x + threadIdx.x;   // 25088 threads
    float4 z = make_float4(0.f, 0.f, 0.f, 0.f);
    if (i < N_NODES / 4)         reinterpret_cast<int4*>(g_deg)[i]   = make_int4(0, 0, 0, 0);
    if (i < (NGRAPH * HID) / 4)  reinterpret_cast<float4*>(g_pooled)[i] = z;
    if (i < NGRAPH / 4)          reinterpret_cast<float4*>(g_cnt)[i] = z;
    if (i == 0) {
        int all0 = 1;
        #pragma unroll
        for (int k = 0; k < 64; k++) {
            if (e[2 * k + 1] != 0u) { all0 = 0; break; }
        }
        g_is64 = all0;
    }
}

// -------- 2. in-degree over dst (4 edges/thread, vector index loads) ------
__global__ void degree_kernel(const void* __restrict__ eidx) {
    int i = blockIdx.x * blockDim.x + threadIdx.x;
    if (i >= N_EDGES / 4) return;
    if (g_is64) {
        const longlong2* p = (const longlong2*)eidx + N_EDGES / 2;  // dst base
        longlong2 a = __ldg(p + 2 * i);
        longlong2 b = __ldg(p + 2 * i + 1);
        atomicAdd(&g_deg[(int)a.x], 1);
        atomicAdd(&g_deg[(int)a.y], 1);
        atomicAdd(&g_deg[(int)b.x], 1);
        atomicAdd(&g_deg[(int)b.y], 1);
    } else {
        const int4* p = (const int4*)eidx + N_EDGES / 4;            // dst base
        int4 a = __ldg(p + i);
        atomicAdd(&g_deg[a.x], 1);
        atomicAdd(&g_deg[a.y], 1);
        atomicAdd(&g_deg[a.z], 1);
        atomicAdd(&g_deg[a.w], 1);
    }
}

// -------- 3. exclusive prefix-sum of deg -> rowptr, wpos ------------------
// Single block, 1024 threads, 98-node serial chunks + Hillis-Steele scan.
__global__ void scan_kernel() {
    __shared__ int s[1024];
    const int t = threadIdx.x;
    const int CH = (N_NODES + 1023) / 1024;          // 98
    const int start = t * CH;
    const int end = min(start + CH, N_NODES);        // empty for large t: ok
    int sum = 0;
    for (int i = start; i < end; i++) sum += g_deg[i];
    s[t] = sum;
    __syncthreads();
    for (int d = 1; d < 1024; d <<= 1) {
        int add = (t >= d) ? s[t - d] : 0;
        __syncthreads();
        s[t] += add;
        __syncthreads();
    }
    int run = s[t] - sum;                            // exclusive prefix
    for (int i = start; i < end; i++) {
        g_rowptr[i] = run;
        g_wpos[i]  = run;
        run += g_deg[i];
    }
    if (t == 1023) g_rowptr[N_NODES] = run;          // == N_EDGES
}

// -------- 4. dinv = rsqrt(deg + self_loop), 4 nodes/thread ----------------
__global__ void dinv_kernel() {
    int i = blockIdx.x * blockDim.x + threadIdx.x;
    if (i >= N_NODES / 4) return;
    int4 d = reinterpret_cast<const int4*>(g_deg)[i];
    float4 r;
    r.x = rsqrtf((float)(d.x + 1));
    r.y = rsqrtf((float)(d.y + 1));
    r.z = rsqrtf((float)(d.z + 1));
    r.w = rsqrtf((float)(d.w + 1));
    reinterpret_cast<float4*>(g_dinv)[i] = r;
}

// -------- 5. h' = (x @ W_conv) * dinv[row] -------------------------------
// Register-blocked: TM=8 rows x TN=4 channels per thread (32 accumulators).
// W staged once in smem; x via direct __ldg (2 distinct 16B addresses per
// warp-load, L1-resident). LDS/FMA 5B -> 0.5B (round-10 ncu: 94% L1).
__global__ __launch_bounds__(256) void gemm1_kernel(const float* __restrict__ x,
                                                    const float* __restrict__ W) {
    __shared__ __align__(16) float Ws[IN_CH * HID];   // 32 KB, [k][ch]

    const int tx = threadIdx.x;          // 0..15 -> channels 4*tx..4*tx+3
    const int ty = threadIdx.y;          // 0..15 -> 8-row group
    const int tid = ty * 16 + tx;

    #pragma unroll
    for (int i = 0; i < 8; i++)
        reinterpret_cast<float4*>(Ws)[tid + i * 256] =
            reinterpret_cast<const float4*>(W)[tid + i * 256];
    __syncthreads();

    const int row0 = blockIdx.x * 128 + ty * 8;
    float4 acc[8];
    #pragma unroll
    for (int i = 0; i < 8; i++) acc[i] = make_float4(0.f, 0.f, 0.f, 0.f);

    const float4* xp = reinterpret_cast<const float4*>(x) + (size_t)row0 * (IN_CH / 4);
    const float* wsc = Ws + 4 * tx;

    if (row0 + 8 <= N_NODES) {
        #pragma unroll 4
        for (int kc = 0; kc < IN_CH / 4; kc++) {
            float4 w0 = *reinterpret_cast<const float4*>(wsc + (4 * kc + 0) * HID);
            float4 w1 = *reinterpret_cast<const float4*>(wsc + (4 * kc + 1) * HID);
            float4 w2 = *reinterpret_cast<const float4*>(wsc + (4 * kc + 2) * HID);
            float4 w3 = *reinterpret_cast<const float4*>(wsc + (4 * kc + 3) * HID);
            #pragma unroll
            for (int i = 0; i < 8; i++) {
                float4 xv = __ldg(xp + i * (IN_CH / 4) + kc);
                acc[i].x = fmaf(xv.x, w0.x, acc[i].x); acc[i].y = fmaf(xv.x, w0.y, acc[i].y);
                acc[i].z = fmaf(xv.x, w0.z, acc[i].z); acc[i].w = fmaf(xv.x, w0.w, acc[i].w);
                acc[i].x = fmaf(xv.y, w1.x, acc[i].x); acc[i].y = fmaf(xv.y, w1.y, acc[i].y);
                acc[i].z = fmaf(xv.y, w1.z, acc[i].z); acc[i].w = fmaf(xv.y, w1.w, acc[i].w);
                acc[i].x = fmaf(xv.z, w2.x, acc[i].x); acc[i].y = fmaf(xv.z, w2.y, acc[i].y);
                acc[i].z = fmaf(xv.z, w2.z, acc[i].z); acc[i].w = fmaf(xv.z, w2.w, acc[i].w);
                acc[i].x = fmaf(xv.w, w3.x, acc[i].x); acc[i].y = fmaf(xv.w, w3.y, acc[i].y);
                acc[i].z = fmaf(xv.w, w3.z, acc[i].z); acc[i].w = fmaf(xv.w, w3.w, acc[i].w);
            }
        }
        #pragma unroll
        for (int i = 0; i < 8; i++) {
            const size_t row = (size_t)(row0 + i);
            const float di = g_dinv[row];
            float4 a = acc[i];
            a.x *= di; a.y *= di; a.z *= di; a.w *= di;
            reinterpret_cast<float4*>(g_h + row * HID)[tx] = a;
        }
    } else {
        #pragma unroll 4
        for (int kc = 0; kc < IN_CH / 4; kc++) {
            float4 w0 = *reinterpret_cast<const float4*>(wsc + (4 * kc + 0) * HID);
            float4 w1 = *reinterpret_cast<const float4*>(wsc + (4 * kc + 1) * HID);
            float4 w2 = *reinterpret_cast<const float4*>(wsc + (4 * kc + 2) * HID);
            float4 w3 = *reinterpret_cast<const float4*>(wsc + (4 * kc + 3) * HID);
            #pragma unroll
            for (int i = 0; i < 8; i++) {
                float4 xv = (row0 + i < N_NODES)
                          ? __ldg(xp + i * (IN_CH / 4) + kc)
                          : make_float4(0.f, 0.f, 0.f, 0.f);
                acc[i].x = fmaf(xv.x, w0.x, acc[i].x); acc[i].y = fmaf(xv.x, w0.y, acc[i].y);
                acc[i].z = fmaf(xv.x, w0.z, acc[i].z); acc[i].w = fmaf(xv.x, w0.w, acc[i].w);
                acc[i].x = fmaf(xv.y, w1.x, acc[i].x); acc[i].y = fmaf(xv.y, w1.y, acc[i].y);
                acc[i].z = fmaf(xv.y, w1.z, acc[i].z); acc[i].w = fmaf(xv.y, w1.w, acc[i].w);
                acc[i].x = fmaf(xv.z, w2.x, acc[i].x); acc[i].y = fmaf(xv.z, w2.y, acc[i].y);
                acc[i].z = fmaf(xv.z, w2.z, acc[i].z); acc[i].w = fmaf(xv.z, w2.w, acc[i].w);
                acc[i].x = fmaf(xv.w, w3.x, acc[i].x); acc[i].y = fmaf(xv.w, w3.y, acc[i].y);
                acc[i].z = fmaf(xv.w, w3.z, acc[i].z); acc[i].w = fmaf(xv.w, w3.w, acc[i].w);
            }
        }
        #pragma unroll
        for (int i = 0; i < 8; i++) {
            if (row0 + i >= N_NODES) break;
            const size_t row = (size_t)(row0 + i);
            const float di = g_dinv[row];
            float4 a = acc[i];
            a.x *= di; a.y *= di; a.z *= di; a.w *= di;
            reinterpret_cast<float4*>(g_h + row * HID)[tx] = a;
        }
    }
}

// -------- 6. CSR bin fill: esrc[wpos[dst]++] = src ------------------------
__global__ void fill_kernel(const void* __restrict__ eidx) {
    int i = blockIdx.x * blockDim.x + threadIdx.x;
    if (i >= N_EDGES / 4) return;
    int s0, s1, s2, s3, d0, d1, d2, d3;
    if (g_is64) {
        const longlong2* ps = (const longlong2*)eidx;
        longlong2 a = __ldg(ps + 2 * i), b = __ldg(ps + 2 * i + 1);
        const longlong2* pd = ps + N_EDGES / 2;
        longlong2 c = __ldg(pd + 2 * i), d = __ldg(pd + 2 * i + 1);
        s0 = (int)a.x; s1 = (int)a.y; s2 = (int)b.x; s3 = (int)b.y;
        d0 = (int)c.x; d1 = (int)c.y; d2 = (int)d.x; d3 = (int)d.y;
    } else {
        const int4* ps = (const int4*)eidx;
        int4 a = __ldg(ps + i);
        int4 b = __ldg(ps + N_EDGES / 4 + i);
        s0 = a.x; s1 = a.y; s2 = a.z; s3 = a.w;
        d0 = b.x; d1 = b.y; d2 = b.z; d3 = b.w;
    }
    g_esrc[atomicAdd(&g_wpos[d0], 1)] = s0;
    g_esrc[atomicAdd(&g_wpos[d1], 1)] = s1;
    g_esrc[atomicAdd(&g_wpos[d2], 1)] = s2;
    g_esrc[atomicAdd(&g_wpos[d3], 1)] = s3;
}

// -------- 7. CSR gather: agg[n] = dinv[n] * sum_{e in bin(n)} h'[src_e] ---
// One warp per node (lane -> 2 channels, float2). Broadcast index loads,
// fully coalesced 256B row gathers (L2-resident h'), 2-way unroll for MLP,
// one coalesced STG per node. No atomics. 100000/8 = 12500 blocks exactly.
__global__ __launch_bounds__(256) void gather_kernel() {
    int node = (blockIdx.x << 3) | (threadIdx.x >> 5);
    int lane = threadIdx.x & 31;
    int beg = __ldg(&g_rowptr[node]);
    int end2 = __ldg(&g_rowptr[node + 1]);

    float2 sum = make_float2(0.f, 0.f);
    int e = beg;
    for (; e + 2 <= end2; e += 2) {
        int s0 = __ldg(&g_esrc[e]);
        int s1 = __ldg(&g_esrc[e + 1]);
        float2 v0 = *reinterpret_cast<const float2*>(g_h + (size_t)s0 * HID + 2 * lane);
        float2 v1 = *reinterpret_cast<const float2*>(g_h + (size_t)s1 * HID + 2 * lane);
        sum.x += v0.x + v1.x;
        sum.y += v0.y + v1.y;
    }
    if (e < end2) {
        int s0 = __ldg(&g_esrc[e]);
        float2 v0 = *reinterpret_cast<const float2*>(g_h + (size_t)s0 * HID + 2 * lane);
        sum.x += v0.x;
        sum.y += v0.y;
    }
    const float dn = g_dinv[node];
    *reinterpret_cast<float2*>(g_agg + (size_t)node * HID + 2 * lane) =
        make_float2(sum.x * dn, sum.y * dn);
}

// -------- 8. self-loop + bias + relu + mean-pool accumulation -------------
#define POOL_BLOCKS 64
#define NSLICES (POOL_BLOCKS * 8)
__global__ void pool_kernel(const void* __restrict__ batch,
                            const float* __restrict__ b_conv) {
    const int c2 = threadIdx.x;          // 0..31 -> channels 2*c2, 2*c2+1
    const int slice = blockIdx.x * 8 + threadIdx.y;
    const int CHUNK = ((N_NODES + NSLICES - 1) / NSLICES + 3) & ~3;  // 4-aligned
    int start = slice * CHUNK;
    int end = min(start + CHUNK, N_NODES);
    if (start >= end) return;

    const int is64 = g_is64;
    const float2 bc = *reinterpret_cast<const float2*>(b_conv + 2 * c2);

    float2 acc = make_float2(0.f, 0.f);
    float cacc = 0.f;
    int cur = is64 ? (int)((const long long*)batch)[start]
                   : ((const int*)batch)[start];

    for (int i0 = start; i0 < end; i0 += 4) {
        int gid[4];
        if (is64) {
            longlong2 a = __ldg((const longlong2*)batch + i0 / 2);
            longlong2 b = __ldg((const longlong2*)batch + i0 / 2 + 1);
            gid[0] = (int)a.x; gid[1] = (int)a.y;
            gid[2] = (int)b.x; gid[3] = (int)b.y;
        } else {
            int4 a = __ldg((const int4*)batch + i0 / 4);
            gid[0] = a.x; gid[1] = a.y; gid[2] = a.z; gid[3] = a.w;
        }
        #pragma unroll
        for (int u = 0; u < 4; u++) {
            int i = i0 + u;
            if (i >= end) break;
            int g = gid[u];
            if (g != cur) {
                atomicAdd(&g_pooled[cur * HID + 2 * c2],     acc.x);
                atomicAdd(&g_pooled[cur * HID + 2 * c2 + 1], acc.y);
                if (c2 == 0) atomicAdd(&g_cnt[cur], cacc);
                acc = make_float2(0.f, 0.f); cacc = 0.f; cur = g;
            }
            const float di = g_dinv[i];
            float2 av = *reinterpret_cast<const float2*>(
                            g_agg + (size_t)i * HID + 2 * c2);
            float2 hv = *reinterpret_cast<const float2*>(
                            g_h + (size_t)i * HID + 2 * c2);
            acc.x += fmaxf(fmaf(hv.x, di, av.x) + bc.x, 0.f);
            acc.y += fmaxf(fmaf(hv.y, di, av.y) + bc.y, 0.f);
            cacc += 1.f;
        }
    }
    atomicAdd(&g_pooled[cur * HID + 2 * c2],     acc.x);
    atomicAdd(&g_pooled[cur * HID + 2 * c2 + 1], acc.y);
    if (c2 == 0) atomicAdd(&g_cnt[cur], cacc);
}

// -------- 9. out = (pooled / cnt) @ W_lin + b_lin --------
__global__ void final_kernel(const float* __restrict__ Wl,
                             const float* __restrict__ bl,
                             float* __restrict__ out) {
    __shared__ float Ws[HID * OUT_CH];
    const int g = threadIdx.x;
    for (int i = g; i < HID * OUT_CH; i += 256) Ws[i] = Wl[i];
    __syncthreads();

    float inv = 1.f / fmaxf(g_cnt[g], 1.f);
    float p[HID];
    #pragma unroll
    for (int k = 0; k < HID; k++) p[k] = g_pooled[g * HID + k] * inv;

    #pragma unroll
    for (int o = 0; o < OUT_CH; o++) {
        float acc = bl[o];
        #pragma unroll
        for (int k = 0; k < HID; k++)
            acc = fmaf(p[k], Ws[k * OUT_CH + o], acc);
        out[g * OUT_CH + o] = acc;
    }
}

// -------- launch --------
extern "C" void kernel_launch(void* const* d_in, const int* in_sizes, int n_in,
                              void* d_out, int out_size) {
    const float* x    = (const float*)d_in[0];
    const void*  eidx = d_in[1];
    const void*  batch= d_in[2];
    const float* Wc   = (const float*)d_in[3];
    const float* bc   = (const float*)d_in[4];
    const float* Wl   = (const float*)d_in[5];
    const float* bl   = (const float*)d_in[6];
    float* out = (float*)d_out;

    zero_kernel<<<98, 256>>>((const unsigned int*)eidx);
    degree_kernel<<<(N_EDGES / 4 + 255) / 256, 256>>>(eidx);
    scan_kernel<<<1, 1024>>>();
    dinv_kernel<<<(N_NODES / 4 + 255) / 256, 256>>>();
    gemm1_kernel<<<(N_NODES + 127) / 128, dim3(16, 16)>>>(x, Wc);
    fill_kernel<<<(N_EDGES / 4 + 255) / 256, 256>>>(eidx);
    gather_kernel<<<N_NODES / 8, 256>>>();
    pool_kernel<<<POOL_BLOCKS, dim3(32, 8)>>>(batch, bc);
    final_kernel<<<1, 256>>>(Wl, bl, out);
}